// round 8
// baseline (speedup 1.0000x reference)
#include <cuda_runtime.h>
#include <cuda_bf16.h>
#include <cstdint>

// CrossAttentionModel_20684562497797
//
// Reference math collapses: softmax over a size-1 axis == 1.0 exactly for any
// finite input; mean over heads of ones == 1.0. Output is ones((2048,2048))
// independent of all inputs -> only mandatory work: write 16 MiB of 1.0f.
//
// R6 post-mortem: TMA bulk-copy version was a per-CTA latency chain (fence +
// single UBLKCP + wait tail) and regressed. The R5 STG version lost time to a
// runtime-trip grid-stride loop (IMAD/ISETP/BRA per store, no store batching).
//
// R7: loop-free single-wave fill. 2048 CTAs x 256 threads, each thread issues
// exactly two independent STG.128s (fully static addressing), then exits.
// 2048 CTAs x 8 warps ~= 0.87 of one full-occupancy wave on 148 SMs: no wave
// transition, no loop carry. Store time floor: 16.7MB / ~6300 B/cyc ~= 1.3us.

static constexpr int THREADS = 256;
static constexpr int V4_PER_THREAD = 2;
static constexpr int V4_PER_CTA = THREADS * V4_PER_THREAD;  // 512 float4 = 8 KiB

__global__ __launch_bounds__(THREADS)
void fill_ones_flat_kernel(float4* __restrict__ out4, int n4) {
    const float4 one4 = make_float4(1.0f, 1.0f, 1.0f, 1.0f);
    int base = blockIdx.x * V4_PER_CTA + threadIdx.x;

    // Two independent, coalesced STG.128s. For this problem n4 = 1M and the
    // grid covers it exactly; guards are predicated-out cheap insurance.
    int i0 = base;
    int i1 = base + THREADS;
    if (i0 < n4) out4[i0] = one4;
    if (i1 < n4) out4[i1] = one4;
}

__global__ void fill_ones_tail_kernel(float* __restrict__ out, int start, int n) {
    int i = start + blockIdx.x * blockDim.x + threadIdx.x;
    if (i < n) out[i] = 1.0f;
}

extern "C" void kernel_launch(void* const* d_in, const int* in_sizes, int n_in,
                              void* d_out, int out_size) {
    (void)d_in; (void)in_sizes; (void)n_in;

    float* out = (float*)d_out;
    int n4 = out_size / 4;  // 1,048,576 for 2048x2048

    int blocks = (n4 + V4_PER_CTA - 1) / V4_PER_CTA;  // 2048
    fill_ones_flat_kernel<<<blocks, THREADS>>>((float4*)out, n4);

    // Robustness tail for out_size not divisible by 4 (not hit here).
    int tail = out_size - n4 * 4;
    if (tail > 0) {
        fill_ones_tail_kernel<<<1, 128>>>(out, n4 * 4, out_size);
    }
}

// round 9
// speedup vs baseline: 4.0048x; 4.0048x over previous
#include <cuda_runtime.h>
#include <cuda_bf16.h>
#include <cstdint>

// CrossAttentionModel_20684562497797
//
// Reference math collapses: softmax over a size-1 axis == 1.0 exactly for any
// finite input; mean over heads of ones == 1.0. Output is ones((2048,2048))
// independent of all inputs -> only mandatory work: write 16 MiB of 1.0f.
//
// R8 post-mortem: kernel duration is pinned at ~5.5us across grid-stride STG,
// TMA bulk-copy, and flat STG variants, with L2 ~26% and issue ~15% in all of
// them -> the kernel sits on a fixed launch/ramp + store-drain floor, not an
// issue or bandwidth limit. ~1.3us of it is mandatory L2 store time
// (16.7MB / ~6300 B/cyc); the rest is overhead no code change has moved.
//
// Final form: one wave, 512 CTAs x 256 threads x 8 STG.128 each (compile-time
// trip count -> ptxas front-batches all 8 stores, MLP=8/thread), exact cover
// of 1M float4, single kernel node always (tail handled by predicates).

static constexpr int THREADS = 256;
static constexpr int V4_PER_THREAD = 8;
static constexpr int V4_PER_CTA = THREADS * V4_PER_THREAD;  // 2048 float4 = 32 KiB

__global__ __launch_bounds__(THREADS)
void fill_ones_kernel(float4* __restrict__ out4, int n4,
                      float* __restrict__ out, int n_total) {
    const float4 one4 = make_float4(1.0f, 1.0f, 1.0f, 1.0f);
    int base = blockIdx.x * V4_PER_CTA + threadIdx.x;

    // 8 independent coalesced STG.128s, statically unrolled. For the real
    // shape (n4 = 1M, grid = 512) every guard is uniformly true.
    #pragma unroll
    for (int j = 0; j < V4_PER_THREAD; j++) {
        int i = base + j * THREADS;
        if (i < n4) out4[i] = one4;
    }

    // Scalar tail for out_size % 4 != 0 (never hit for 2048x2048); keeps the
    // graph a single kernel node for any out_size.
    if (blockIdx.x == 0) {
        int t = n4 * 4 + threadIdx.x;
        if (t < n_total) out[t] = 1.0f;
    }
}

extern "C" void kernel_launch(void* const* d_in, const int* in_sizes, int n_in,
                              void* d_out, int out_size) {
    (void)d_in; (void)in_sizes; (void)n_in;

    float* out = (float*)d_out;
    int n4 = out_size / 4;                              // 1,048,576
    int blocks = (n4 + V4_PER_CTA - 1) / V4_PER_CTA;    // 512
    if (blocks < 1) blocks = 1;

    fill_ones_kernel<<<blocks, THREADS>>>((float4*)out, n4, out, out_size);
}